// round 11
// baseline (speedup 1.0000x reference)
#include <cuda_runtime.h>
#include <cuda_bf16.h>
#include <cstdint>

#define ROWS 4096
#define COLS 11008
#define RANK 32
#define GROUPS_PER_ROW 1376   // COLS/8
#define I_SPLIT_BY 16         // blockIdx.y >= 16 -> codebook 1

#define TI 128
#define TJ 128
#define THREADS 256

#define BS_STRIDE 40          // bf16 (conflict-free B frag loads)
#define CB_PLANE_FLOATS 520   // 256 entries * 2 floats + 8 pad -> plane stride == 4 mod 16 bank-pairs
#define OB_STRIDE 36          // floats per staged row: 32 data + 4 pad; 144B (16B-mult)

#define BS_BYTES (TJ * BS_STRIDE * 2)          // 10240
#define CBS_BYTES (4 * CB_PLANE_FLOATS * 4)    // 8320
#define OB_WARP_FLOATS (16 * OB_STRIDE)        // 576
#define OB_BUF_BYTES (8 * OB_WARP_FLOATS * 4)  // 18432 per buffer
#define SMEM_TOTAL (BS_BYTES + CBS_BYTES + 2 * OB_BUF_BYTES)  // 55424

static __device__ __forceinline__ uint32_t smem_u32(const void* p) {
    uint32_t a;
    asm("{ .reg .u64 t; cvta.to.shared.u64 t, %1; cvt.u32.u64 %0, t; }" : "=r"(a) : "l"(p));
    return a;
}
static __device__ __forceinline__ uint32_t pk_bf16x2(float2 v) {
    uint32_t r;
    asm("cvt.rn.bf16x2.f32 %0, %1, %2;" : "=r"(r) : "f"(v.y), "f"(v.x));
    return r;
}

__global__ __launch_bounds__(THREADS, 4)
void qw_tma6_kernel(const float* __restrict__ codebooks,  // (2,256,8)
                    const int*   __restrict__ codes,      // flat
                    const float* __restrict__ scales,     // (11008,)
                    const float* __restrict__ L,          // (4096,32)
                    const float* __restrict__ R,          // (32,11008)
                    float*       __restrict__ out)        // (4096,11008)
{
    extern __shared__ __align__(16) char smem[];
    __nv_bfloat16* Bs   = reinterpret_cast<__nv_bfloat16*>(smem);
    float*         cbs  = reinterpret_cast<float*>(smem + BS_BYTES);
    float*         obuf = reinterpret_cast<float*>(smem + BS_BYTES + CBS_BYTES);

    const int tid = threadIdx.x;
    const int wid = tid >> 5;
    const int lid = tid & 31;
    const int i0  = blockIdx.y * TI;
    const int j0  = blockIdx.x * TJ;

    // ---- stage THIS CTA's codebook as 4 q-planes (plane q: entry's float2 at offset 2q) ----
    {
        const float* cb_src = codebooks + ((blockIdx.y >= I_SPLIT_BY) ? 2048 : 0);
        #pragma unroll
        for (int idx = tid; idx < 1024; idx += THREADS) {
            int e = idx & 255, qq = idx >> 8;
            float2 v = *reinterpret_cast<const float2*>(cb_src + e * 8 + 2 * qq);
            *reinterpret_cast<float2*>(cbs + qq * CB_PLANE_FLOATS + e * 2) = v;
        }
    }
    // ---- stage B = R^T tile [128n x 32k] bf16 ----
    #pragma unroll
    for (int idx = tid; idx < TJ * RANK; idx += THREADS) {
        int k = idx >> 7, n = idx & 127;
        Bs[n * BS_STRIDE + k] = __float2bfloat16(R[k * COLS + j0 + n]);
    }
    __syncthreads();

    // ---- fragment identity ----
    const int rfrag = lid >> 2;
    const int q     = lid & 3;
    const int r0    = wid * 16 + rfrag;
    const int r1    = r0 + 8;
    const int gi0   = i0 + r0;
    const int gi1   = i0 + r1;

    // ---- A fragments straight from gmem (L2-hot) ----
    const float* L0 = L + (size_t)gi0 * RANK;
    const float* L1 = L + (size_t)gi1 * RANK;
    uint32_t a0 = pk_bf16x2(*reinterpret_cast<const float2*>(L0 + 2 * q));
    uint32_t a1 = pk_bf16x2(*reinterpret_cast<const float2*>(L1 + 2 * q));
    uint32_t a2 = pk_bf16x2(*reinterpret_cast<const float2*>(L0 + 2 * q + 8));
    uint32_t a3 = pk_bf16x2(*reinterpret_cast<const float2*>(L1 + 2 * q + 8));
    uint32_t a4 = pk_bf16x2(*reinterpret_cast<const float2*>(L0 + 16 + 2 * q));
    uint32_t a5 = pk_bf16x2(*reinterpret_cast<const float2*>(L1 + 16 + 2 * q));
    uint32_t a6 = pk_bf16x2(*reinterpret_cast<const float2*>(L0 + 24 + 2 * q));
    uint32_t a7 = pk_bf16x2(*reinterpret_cast<const float2*>(L1 + 24 + 2 * q));

    const unsigned base0 = (unsigned)gi0 * COLS + (unsigned)j0;
    const unsigned base1 = (unsigned)gi1 * COLS + (unsigned)j0;
    const int sidx0 = (int)(base0 >> 12);
    const int sidx1 = (int)(base1 >> 12);
    const int tB0 = (int)((4096u - (base0 & 4095u) + 7u) >> 3);
    const int tB1 = (int)((4096u - (base1 & 4095u) + 7u) >> 3);
    const float sLo0 = __ldg(&scales[sidx0]);
    const float sHi0 = __ldg(&scales[(sidx0 + 1 < COLS) ? sidx0 + 1 : COLS - 1]);
    const float sLo1 = __ldg(&scales[sidx1]);
    const float sHi1 = __ldg(&scales[(sidx1 + 1 < COLS) ? sidx1 + 1 : COLS - 1]);

    // ---- codes: 16B-aligned int4 chunks straight from gmem, prefetched ----
    const int4* cp0 = reinterpret_cast<const int4*>(codes + (size_t)gi0 * GROUPS_PER_ROW + (j0 >> 3));
    const int4* cp1 = reinterpret_cast<const int4*>(codes + (size_t)gi1 * GROUPS_PER_ROW + (j0 >> 3));
    int4 cc0 = __ldg(cp0);
    int4 cc1 = __ldg(cp1);

    // per-thread codebook plane base
    const float* cbq = cbs + q * CB_PLANE_FLOATS;

    const unsigned gdst_row = (unsigned)(i0 + wid * 16 + lid) * COLS + (unsigned)j0;

    #pragma unroll
    for (int ch = 0; ch < 4; ch++) {
        const int buf = ch & 1;
        float* ob = obuf + buf * (OB_BUF_BYTES / 4) + wid * OB_WARP_FLOATS;
        float* st0 = ob + rfrag * OB_STRIDE + 2 * q;
        float* st1 = ob + (rfrag + 8) * OB_STRIDE + 2 * q;

        // prefetch next chunk's codes
        int4 nn0, nn1;
        if (ch < 3) { nn0 = __ldg(cp0 + ch + 1); nn1 = __ldg(cp1 + ch + 1); }

        // double buffering: allow 1 outstanding TMA group (prev chunk), require
        // the chunk-2 group (same buffer) to have finished READING smem.
        if (ch > 1) {
            asm volatile("cp.async.bulk.wait_group.read 1;" ::: "memory");
            __syncwarp();
        }

        const int c0a[4] = {cc0.x, cc0.y, cc0.z, cc0.w};
        const int c1a[4] = {cc1.x, cc1.y, cc1.z, cc1.w};

        // software pipeline: preload B fragments for tt=0
        uint32_t b0, b1, b2, b3;
        {
            const int nb = (ch * 4 * 8 + rfrag) * BS_STRIDE;
            b0 = *reinterpret_cast<const uint32_t*>(&Bs[nb + 2 * q]);
            b1 = *reinterpret_cast<const uint32_t*>(&Bs[nb + 2 * q + 8]);
            b2 = *reinterpret_cast<const uint32_t*>(&Bs[nb + 16 + 2 * q]);
            b3 = *reinterpret_cast<const uint32_t*>(&Bs[nb + 16 + 2 * q + 8]);
        }

        #pragma unroll
        for (int tt = 0; tt < 4; tt++) {
            const int t = ch * 4 + tt;

            float c0 = 0.f, c1 = 0.f, c2 = 0.f, c3 = 0.f;
            asm volatile(
                "mma.sync.aligned.m16n8k16.row.col.f32.bf16.bf16.f32 "
                "{%0,%1,%2,%3}, {%4,%5,%6,%7}, {%8,%9}, {%0,%1,%2,%3};"
                : "+f"(c0), "+f"(c1), "+f"(c2), "+f"(c3)
                : "r"(a0), "r"(a1), "r"(a2), "r"(a3), "r"(b0), "r"(b1));
            asm volatile(
                "mma.sync.aligned.m16n8k16.row.col.f32.bf16.bf16.f32 "
                "{%0,%1,%2,%3}, {%4,%5,%6,%7}, {%8,%9}, {%0,%1,%2,%3};"
                : "+f"(c0), "+f"(c1), "+f"(c2), "+f"(c3)
                : "r"(a4), "r"(a5), "r"(a6), "r"(a7), "r"(b2), "r"(b3));

            // load next tile's B fragments while MMAs are in flight
            if (tt < 3) {
                const int nb = ((t + 1) * 8 + rfrag) * BS_STRIDE;
                b0 = *reinterpret_cast<const uint32_t*>(&Bs[nb + 2 * q]);
                b1 = *reinterpret_cast<const uint32_t*>(&Bs[nb + 2 * q + 8]);
                b2 = *reinterpret_cast<const uint32_t*>(&Bs[nb + 16 + 2 * q]);
                b3 = *reinterpret_cast<const uint32_t*>(&Bs[nb + 16 + 2 * q + 8]);
            }

            // codebook gather from q-plane (staggered banks)
            const float2 e0 = *reinterpret_cast<const float2*>(cbq + c0a[tt] * 2);
            const float2 e1 = *reinterpret_cast<const float2*>(cbq + c1a[tt] * 2);
            const float s0 = (t >= tB0) ? sHi0 : sLo0;
            const float s1 = (t >= tB1) ? sHi1 : sLo1;

            *reinterpret_cast<float2*>(st0 + tt * 8) =
                make_float2(fmaf(e0.x, s0, c0), fmaf(e0.y, s0, c1));
            *reinterpret_cast<float2*>(st1 + tt * 8) =
                make_float2(fmaf(e1.x, s1, c2), fmaf(e1.y, s1, c3));
        }
        __syncwarp();
        asm volatile("fence.proxy.async.shared::cta;" ::: "memory");

        if (lid < 16) {
            float* dst = out + gdst_row + (unsigned)(ch * 32);
            uint32_t src = smem_u32(ob) + (uint32_t)(lid * OB_STRIDE * 4);
            asm volatile(
                "cp.async.bulk.global.shared::cta.bulk_group [%0], [%1], 128;"
                :: "l"(dst), "r"(src) : "memory");
        }
        asm volatile("cp.async.bulk.commit_group;" ::: "memory");

        cc0 = nn0; cc1 = nn1;
    }
    asm volatile("cp.async.bulk.wait_group 0;" ::: "memory");
}

extern "C" void kernel_launch(void* const* d_in, const int* in_sizes, int n_in,
                              void* d_out, int out_size) {
    const float* codebooks = (const float*)d_in[0];
    const int*   codes     = (const int*)  d_in[1];
    const float* scales    = (const float*)d_in[2];
    const float* L         = (const float*)d_in[3];
    const float* R         = (const float*)d_in[4];
    float*       out       = (float*)d_out;

    cudaFuncSetAttribute(qw_tma6_kernel,
                         cudaFuncAttributeMaxDynamicSharedMemorySize, SMEM_TOTAL);

    dim3 grid(COLS / TJ, ROWS / TI);   // (86, 32)
    qw_tma6_kernel<<<grid, THREADS, SMEM_TOTAL>>>(codebooks, codes, scales, L, R, out);
}

// round 12
// speedup vs baseline: 1.2209x; 1.2209x over previous
#include <cuda_runtime.h>
#include <cuda_bf16.h>
#include <cstdint>

#define ROWS 4096
#define COLS 11008
#define RANK 32
#define GROUPS_PER_ROW 1376   // COLS/8

#define TI 128
#define TJ 128
#define THREADS 256

#define BS_STRIDE 40          // bf16 (conflict-free B frag loads)
#define CBS_STRIDE 10         // floats (even -> 8B-aligned float2 gathers)
#define OB_STRIDE 36          // floats per staged row: 32 data + 4 pad; 144B

#define BS_BYTES (TJ * BS_STRIDE * 2)          // 10240
#define CBS_BYTES (512 * CBS_STRIDE * 4)       // 20480 (both codebooks)
#define OB_WARP_FLOATS (16 * OB_STRIDE)        // 576
#define OB_BYTES (8 * OB_WARP_FLOATS * 4)      // 18432
#define SMEM_TOTAL (BS_BYTES + CBS_BYTES + OB_BYTES)  // 49152

// persistent grid: 592 CTAs (148 SM x 4), 2752 tiles = 384*5 + 208*4
#define GRID_CTAS 592
#define N_FIVE 384

static __device__ __forceinline__ uint32_t smem_u32(const void* p) {
    uint32_t a;
    asm("{ .reg .u64 t; cvta.to.shared.u64 t, %1; cvt.u32.u64 %0, t; }" : "=r"(a) : "l"(p));
    return a;
}
static __device__ __forceinline__ uint32_t pk_bf16x2(float2 v) {
    uint32_t r;
    asm("cvt.rn.bf16x2.f32 %0, %1, %2;" : "=r"(r) : "f"(v.y), "f"(v.x));
    return r;
}

__global__ __launch_bounds__(THREADS, 4)
void qw_pers_kernel(const float* __restrict__ codebooks,  // (2,256,8)
                    const int*   __restrict__ codes,      // flat
                    const float* __restrict__ scales,     // (11008,)
                    const float* __restrict__ L,          // (4096,32)
                    const float* __restrict__ R,          // (32,11008)
                    float*       __restrict__ out)        // (4096,11008)
{
    extern __shared__ __align__(16) char smem[];
    __nv_bfloat16* Bs   = reinterpret_cast<__nv_bfloat16*>(smem);
    float*         cbs  = reinterpret_cast<float*>(smem + BS_BYTES);
    float*         obuf = reinterpret_cast<float*>(smem + BS_BYTES + CBS_BYTES);

    const int tid = threadIdx.x;
    const int wid = tid >> 5;
    const int lid = tid & 31;

    // ---- persistent tile run: contiguous, i-major (idx = jt*32 + it) ----
    const int c = blockIdx.x;
    int start, cnt;
    if (c < N_FIVE) { start = c * 5;                    cnt = 5; }
    else            { start = N_FIVE * 5 + (c - N_FIVE) * 4; cnt = 4; }

    // ---- stage BOTH codebooks once (stride-10 padded) ----
    #pragma unroll
    for (int e = tid; e < 512; e += THREADS) {
        const float2* s = reinterpret_cast<const float2*>(codebooks + e * 8);
        float2*       d = reinterpret_cast<float2*>(cbs + e * CBS_STRIDE);
        d[0] = s[0]; d[1] = s[1]; d[2] = s[2]; d[3] = s[3];
    }

    // ---- stage B for the first column ----
    int cur_jt = start >> 5;
    {
        const int j0 = cur_jt * TJ;
        #pragma unroll
        for (int idx = tid; idx < TJ * RANK; idx += THREADS) {
            int k = idx >> 7, n = idx & 127;
            Bs[n * BS_STRIDE + k] = __float2bfloat16(R[k * COLS + j0 + n]);
        }
    }
    __syncthreads();

    // ---- fragment identity (tile-invariant) ----
    const int rfrag = lid >> 2;
    const int q     = lid & 3;

    float* ob = obuf + wid * OB_WARP_FLOATS;
    const uint32_t ob_sm = smem_u32(ob);
    float* st0 = ob + rfrag * OB_STRIDE + 2 * q;
    float* st1 = ob + (rfrag + 8) * OB_STRIDE + 2 * q;

    bool have_pending = false;

    #pragma unroll 1
    for (int m = 0; m < cnt; m++) {
        const int idx = start + m;
        const int jt  = idx >> 5;
        const int it  = idx & 31;
        const int i0  = it * TI;
        const int j0  = jt * TJ;

        // restage B on column crossing (rare)
        if (jt != cur_jt) {
            __syncthreads();                       // all warps done reading old Bs
            #pragma unroll
            for (int x = tid; x < TJ * RANK; x += THREADS) {
                int k = x >> 7, n = x & 127;
                Bs[n * BS_STRIDE + k] = __float2bfloat16(R[k * COLS + j0 + n]);
            }
            cur_jt = jt;
            __syncthreads();
        }

        const float* cbt = cbs + ((it >= 16) ? 256 * CBS_STRIDE : 0);

        const int r0  = wid * 16 + rfrag;
        const int r1  = r0 + 8;
        const int gi0 = i0 + r0;
        const int gi1 = i0 + r1;

        // A fragments straight from gmem (L2-hot)
        const float* L0 = L + (size_t)gi0 * RANK;
        const float* L1 = L + (size_t)gi1 * RANK;
        uint32_t a0 = pk_bf16x2(*reinterpret_cast<const float2*>(L0 + 2 * q));
        uint32_t a1 = pk_bf16x2(*reinterpret_cast<const float2*>(L1 + 2 * q));
        uint32_t a2 = pk_bf16x2(*reinterpret_cast<const float2*>(L0 + 2 * q + 8));
        uint32_t a3 = pk_bf16x2(*reinterpret_cast<const float2*>(L1 + 2 * q + 8));
        uint32_t a4 = pk_bf16x2(*reinterpret_cast<const float2*>(L0 + 16 + 2 * q));
        uint32_t a5 = pk_bf16x2(*reinterpret_cast<const float2*>(L1 + 16 + 2 * q));
        uint32_t a6 = pk_bf16x2(*reinterpret_cast<const float2*>(L0 + 24 + 2 * q));
        uint32_t a7 = pk_bf16x2(*reinterpret_cast<const float2*>(L1 + 24 + 2 * q));

        const unsigned base0 = (unsigned)gi0 * COLS + (unsigned)j0;
        const unsigned base1 = (unsigned)gi1 * COLS + (unsigned)j0;
        const int sidx0 = (int)(base0 >> 12);
        const int sidx1 = (int)(base1 >> 12);
        const int tB0 = (int)((4096u - (base0 & 4095u) + 7u) >> 3);
        const int tB1 = (int)((4096u - (base1 & 4095u) + 7u) >> 3);
        const float sLo0 = __ldg(&scales[sidx0]);
        const float sHi0 = __ldg(&scales[(sidx0 + 1 < COLS) ? sidx0 + 1 : COLS - 1]);
        const float sLo1 = __ldg(&scales[sidx1]);
        const float sHi1 = __ldg(&scales[(sidx1 + 1 < COLS) ? sidx1 + 1 : COLS - 1]);

        const int4* cp0 = reinterpret_cast<const int4*>(codes + (size_t)gi0 * GROUPS_PER_ROW + (j0 >> 3));
        const int4* cp1 = reinterpret_cast<const int4*>(codes + (size_t)gi1 * GROUPS_PER_ROW + (j0 >> 3));
        int4 cc0 = __ldg(cp0);
        int4 cc1 = __ldg(cp1);

        const unsigned gdst_row = (unsigned)(i0 + wid * 16 + lid) * COLS + (unsigned)j0;

        #pragma unroll
        for (int ch = 0; ch < 4; ch++) {
            // prefetch next chunk's codes
            int4 nn0, nn1;
            if (ch < 3) { nn0 = __ldg(cp0 + ch + 1); nn1 = __ldg(cp1 + ch + 1); }

            // OB reuse: prior TMA group must have finished reading smem
            if (have_pending) {
                asm volatile("cp.async.bulk.wait_group.read 0;" ::: "memory");
                __syncwarp();
            }

            const int c0a[4] = {cc0.x, cc0.y, cc0.z, cc0.w};
            const int c1a[4] = {cc1.x, cc1.y, cc1.z, cc1.w};

            // software pipeline: preload B fragments for tt=0
            uint32_t b0, b1, b2, b3;
            {
                const int nb = (ch * 32 + rfrag) * BS_STRIDE;
                b0 = *reinterpret_cast<const uint32_t*>(&Bs[nb + 2 * q]);
                b1 = *reinterpret_cast<const uint32_t*>(&Bs[nb + 2 * q + 8]);
                b2 = *reinterpret_cast<const uint32_t*>(&Bs[nb + 16 + 2 * q]);
                b3 = *reinterpret_cast<const uint32_t*>(&Bs[nb + 16 + 2 * q + 8]);
            }

            #pragma unroll
            for (int tt = 0; tt < 4; tt++) {
                const int t = ch * 4 + tt;

                float c0 = 0.f, c1 = 0.f, c2 = 0.f, c3 = 0.f;
                asm volatile(
                    "mma.sync.aligned.m16n8k16.row.col.f32.bf16.bf16.f32 "
                    "{%0,%1,%2,%3}, {%4,%5,%6,%7}, {%8,%9}, {%0,%1,%2,%3};"
                    : "+f"(c0), "+f"(c1), "+f"(c2), "+f"(c3)
                    : "r"(a0), "r"(a1), "r"(a2), "r"(a3), "r"(b0), "r"(b1));
                asm volatile(
                    "mma.sync.aligned.m16n8k16.row.col.f32.bf16.bf16.f32 "
                    "{%0,%1,%2,%3}, {%4,%5,%6,%7}, {%8,%9}, {%0,%1,%2,%3};"
                    : "+f"(c0), "+f"(c1), "+f"(c2), "+f"(c3)
                    : "r"(a4), "r"(a5), "r"(a6), "r"(a7), "r"(b2), "r"(b3));

                if (tt < 3) {
                    const int nb = ((t + 1) * 8 + rfrag) * BS_STRIDE;
                    b0 = *reinterpret_cast<const uint32_t*>(&Bs[nb + 2 * q]);
                    b1 = *reinterpret_cast<const uint32_t*>(&Bs[nb + 2 * q + 8]);
                    b2 = *reinterpret_cast<const uint32_t*>(&Bs[nb + 16 + 2 * q]);
                    b3 = *reinterpret_cast<const uint32_t*>(&Bs[nb + 16 + 2 * q + 8]);
                }

                const float2 e0 = *reinterpret_cast<const float2*>(cbt + c0a[tt] * CBS_STRIDE + 2 * q);
                const float2 e1 = *reinterpret_cast<const float2*>(cbt + c1a[tt] * CBS_STRIDE + 2 * q);
                const float s0 = (t >= tB0) ? sHi0 : sLo0;
                const float s1 = (t >= tB1) ? sHi1 : sLo1;

                *reinterpret_cast<float2*>(st0 + tt * 8) =
                    make_float2(fmaf(e0.x, s0, c0), fmaf(e0.y, s0, c1));
                *reinterpret_cast<float2*>(st1 + tt * 8) =
                    make_float2(fmaf(e1.x, s1, c2), fmaf(e1.y, s1, c3));
            }
            __syncwarp();
            asm volatile("fence.proxy.async.shared::cta;" ::: "memory");

            if (lid < 16) {
                float* dst = out + gdst_row + (unsigned)(ch * 32);
                uint32_t src = ob_sm + (uint32_t)(lid * OB_STRIDE * 4);
                asm volatile(
                    "cp.async.bulk.global.shared::cta.bulk_group [%0], [%1], 128;"
                    :: "l"(dst), "r"(src) : "memory");
            }
            asm volatile("cp.async.bulk.commit_group;" ::: "memory");
            have_pending = true;

            cc0 = nn0; cc1 = nn1;
        }
    }
    asm volatile("cp.async.bulk.wait_group 0;" ::: "memory");
}

extern "C" void kernel_launch(void* const* d_in, const int* in_sizes, int n_in,
                              void* d_out, int out_size) {
    const float* codebooks = (const float*)d_in[0];
    const int*   codes     = (const int*)  d_in[1];
    const float* scales    = (const float*)d_in[2];
    const float* L         = (const float*)d_in[3];
    const float* R         = (const float*)d_in[4];
    float*       out       = (float*)d_out;

    cudaFuncSetAttribute(qw_pers_kernel,
                         cudaFuncAttributeMaxDynamicSharedMemorySize, SMEM_TOTAL);

    qw_pers_kernel<<<GRID_CTAS, THREADS, SMEM_TOTAL>>>(codebooks, codes, scales, L, R, out);
}

// round 13
// speedup vs baseline: 1.2351x; 1.0116x over previous
#include <cuda_runtime.h>
#include <cuda_bf16.h>
#include <cstdint>

#define ROWS 4096
#define COLS 11008
#define RANK 32
#define GROUPS_PER_ROW 1376   // COLS/8

#define TI 128
#define TJ 128
#define THREADS 256

#define BS_STRIDE 40          // bf16 (conflict-free B frag loads)
#define CBS_STRIDE 10         // floats (even -> 8B-aligned float2 gathers)
#define OB_STRIDE 68          // floats per staged row: 64 data + 4 pad; 272B (16B-mult)

#define BS_BYTES (TJ * BS_STRIDE * 2)          // 10240
#define CBS_BYTES (512 * CBS_STRIDE * 4)       // 20480 (both codebooks)
#define OB_WARP_FLOATS (16 * OB_STRIDE)        // 1088
#define OB_BYTES (8 * OB_WARP_FLOATS * 4)      // 34816
#define SMEM_TOTAL (BS_BYTES + CBS_BYTES + OB_BYTES)  // 65536 (64KB -> 3 CTAs/SM)

// persistent grid: one wave at 3 CTAs/SM = 444 CTAs; 2752 tiles = 88*7 + 356*6
#define GRID_CTAS 444
#define N_SEVEN 88

static __device__ __forceinline__ uint32_t smem_u32(const void* p) {
    uint32_t a;
    asm("{ .reg .u64 t; cvta.to.shared.u64 t, %1; cvt.u32.u64 %0, t; }" : "=r"(a) : "l"(p));
    return a;
}
static __device__ __forceinline__ uint32_t pk_bf16x2(float2 v) {
    uint32_t r;
    asm("cvt.rn.bf16x2.f32 %0, %1, %2;" : "=r"(r) : "f"(v.y), "f"(v.x));
    return r;
}

__global__ __launch_bounds__(THREADS, 3)
void qw_pers2_kernel(const float* __restrict__ codebooks,  // (2,256,8)
                     const int*   __restrict__ codes,      // flat
                     const float* __restrict__ scales,     // (11008,)
                     const float* __restrict__ L,          // (4096,32)
                     const float* __restrict__ R,          // (32,11008)
                     float*       __restrict__ out)        // (4096,11008)
{
    extern __shared__ __align__(16) char smem[];
    __nv_bfloat16* Bs   = reinterpret_cast<__nv_bfloat16*>(smem);
    float*         cbs  = reinterpret_cast<float*>(smem + BS_BYTES);
    float*         obuf = reinterpret_cast<float*>(smem + BS_BYTES + CBS_BYTES);

    const int tid = threadIdx.x;
    const int wid = tid >> 5;
    const int lid = tid & 31;

    // ---- persistent tile run: contiguous, i-major (idx = jt*32 + it) ----
    const int c = blockIdx.x;
    int start, cnt;
    if (c < N_SEVEN) { start = c * 7;                     cnt = 7; }
    else             { start = N_SEVEN * 7 + (c - N_SEVEN) * 6; cnt = 6; }

    // ---- stage BOTH codebooks once (stride-10 padded) ----
    #pragma unroll
    for (int e = tid; e < 512; e += THREADS) {
        const float2* s = reinterpret_cast<const float2*>(codebooks + e * 8);
        float2*       d = reinterpret_cast<float2*>(cbs + e * CBS_STRIDE);
        d[0] = s[0]; d[1] = s[1]; d[2] = s[2]; d[3] = s[3];
    }

    // ---- stage B for the first column ----
    int cur_jt = start >> 5;
    {
        const int j0 = cur_jt * TJ;
        #pragma unroll
        for (int idx = tid; idx < TJ * RANK; idx += THREADS) {
            int k = idx >> 7, n = idx & 127;
            Bs[n * BS_STRIDE + k] = __float2bfloat16(R[k * COLS + j0 + n]);
        }
    }
    __syncthreads();

    // ---- fragment identity (tile-invariant) ----
    const int rfrag = lid >> 2;
    const int q     = lid & 3;

    float* ob = obuf + wid * OB_WARP_FLOATS;
    const uint32_t ob_sm = smem_u32(ob);
    float* st0 = ob + rfrag * OB_STRIDE + 2 * q;
    float* st1 = ob + (rfrag + 8) * OB_STRIDE + 2 * q;

    bool have_pending = false;

    #pragma unroll 1
    for (int m = 0; m < cnt; m++) {
        const int idx = start + m;
        const int jt  = idx >> 5;
        const int it  = idx & 31;
        const int i0  = it * TI;
        const int j0  = jt * TJ;

        // restage B on column crossing (rare)
        if (jt != cur_jt) {
            __syncthreads();
            #pragma unroll
            for (int x = tid; x < TJ * RANK; x += THREADS) {
                int k = x >> 7, n = x & 127;
                Bs[n * BS_STRIDE + k] = __float2bfloat16(R[k * COLS + j0 + n]);
            }
            cur_jt = jt;
            __syncthreads();
        }

        const float* cbt = cbs + ((it >= 16) ? 256 * CBS_STRIDE : 0);

        const int r0  = wid * 16 + rfrag;
        const int r1  = r0 + 8;
        const int gi0 = i0 + r0;
        const int gi1 = i0 + r1;

        // A fragments straight from gmem (L2-hot)
        const float* L0 = L + (size_t)gi0 * RANK;
        const float* L1 = L + (size_t)gi1 * RANK;
        uint32_t a0 = pk_bf16x2(*reinterpret_cast<const float2*>(L0 + 2 * q));
        uint32_t a1 = pk_bf16x2(*reinterpret_cast<const float2*>(L1 + 2 * q));
        uint32_t a2 = pk_bf16x2(*reinterpret_cast<const float2*>(L0 + 2 * q + 8));
        uint32_t a3 = pk_bf16x2(*reinterpret_cast<const float2*>(L1 + 2 * q + 8));
        uint32_t a4 = pk_bf16x2(*reinterpret_cast<const float2*>(L0 + 16 + 2 * q));
        uint32_t a5 = pk_bf16x2(*reinterpret_cast<const float2*>(L1 + 16 + 2 * q));
        uint32_t a6 = pk_bf16x2(*reinterpret_cast<const float2*>(L0 + 24 + 2 * q));
        uint32_t a7 = pk_bf16x2(*reinterpret_cast<const float2*>(L1 + 24 + 2 * q));

        const unsigned base0 = (unsigned)gi0 * COLS + (unsigned)j0;
        const unsigned base1 = (unsigned)gi1 * COLS + (unsigned)j0;
        const int sidx0 = (int)(base0 >> 12);
        const int sidx1 = (int)(base1 >> 12);
        const int tB0 = (int)((4096u - (base0 & 4095u) + 7u) >> 3);
        const int tB1 = (int)((4096u - (base1 & 4095u) + 7u) >> 3);
        const float sLo0 = __ldg(&scales[sidx0]);
        const float sHi0 = __ldg(&scales[(sidx0 + 1 < COLS) ? sidx0 + 1 : COLS - 1]);
        const float sLo1 = __ldg(&scales[sidx1]);
        const float sHi1 = __ldg(&scales[(sidx1 + 1 < COLS) ? sidx1 + 1 : COLS - 1]);

        const int4* cp0 = reinterpret_cast<const int4*>(codes + (size_t)gi0 * GROUPS_PER_ROW + (j0 >> 3));
        const int4* cp1 = reinterpret_cast<const int4*>(codes + (size_t)gi1 * GROUPS_PER_ROW + (j0 >> 3));
        // chunk 0 codes (8 groups per row = 2 int4)
        int4 cA0 = __ldg(cp0);
        int4 cA1 = __ldg(cp0 + 1);
        int4 cB0 = __ldg(cp1);
        int4 cB1 = __ldg(cp1 + 1);

        const unsigned gdst_row = (unsigned)(i0 + wid * 16 + lid) * COLS + (unsigned)j0;

        #pragma unroll
        for (int ch = 0; ch < 2; ch++) {
            // prefetch chunk-1 codes while chunk-0 computes
            int4 nA0, nA1, nB0, nB1;
            if (ch == 0) {
                nA0 = __ldg(cp0 + 2); nA1 = __ldg(cp0 + 3);
                nB0 = __ldg(cp1 + 2); nB1 = __ldg(cp1 + 3);
            }

            // OB reuse: prior TMA group must have finished reading smem
            if (have_pending) {
                asm volatile("cp.async.bulk.wait_group.read 0;" ::: "memory");
                __syncwarp();
            }

            const int c0a[8] = {cA0.x, cA0.y, cA0.z, cA0.w, cA1.x, cA1.y, cA1.z, cA1.w};
            const int c1a[8] = {cB0.x, cB0.y, cB0.z, cB0.w, cB1.x, cB1.y, cB1.z, cB1.w};

            // software pipeline: preload B fragments for tt=0
            uint32_t b0, b1, b2, b3;
            {
                const int nb = (ch * 64 + rfrag) * BS_STRIDE;
                b0 = *reinterpret_cast<const uint32_t*>(&Bs[nb + 2 * q]);
                b1 = *reinterpret_cast<const uint32_t*>(&Bs[nb + 2 * q + 8]);
                b2 = *reinterpret_cast<const uint32_t*>(&Bs[nb + 16 + 2 * q]);
                b3 = *reinterpret_cast<const uint32_t*>(&Bs[nb + 16 + 2 * q + 8]);
            }

            #pragma unroll
            for (int tt = 0; tt < 8; tt++) {
                const int t = ch * 8 + tt;

                float c0 = 0.f, c1 = 0.f, c2 = 0.f, c3 = 0.f;
                asm volatile(
                    "mma.sync.aligned.m16n8k16.row.col.f32.bf16.bf16.f32 "
                    "{%0,%1,%2,%3}, {%4,%5,%6,%7}, {%8,%9}, {%0,%1,%2,%3};"
                    : "+f"(c0), "+f"(c1), "+f"(c2), "+f"(c3)
                    : "r"(a0), "r"(a1), "r"(a2), "r"(a3), "r"(b0), "r"(b1));
                asm volatile(
                    "mma.sync.aligned.m16n8k16.row.col.f32.bf16.bf16.f32 "
                    "{%0,%1,%2,%3}, {%4,%5,%6,%7}, {%8,%9}, {%0,%1,%2,%3};"
                    : "+f"(c0), "+f"(c1), "+f"(c2), "+f"(c3)
                    : "r"(a4), "r"(a5), "r"(a6), "r"(a7), "r"(b2), "r"(b3));

                if (tt < 7) {
                    const int nb = ((t + 1) * 8 + rfrag) * BS_STRIDE;
                    b0 = *reinterpret_cast<const uint32_t*>(&Bs[nb + 2 * q]);
                    b1 = *reinterpret_cast<const uint32_t*>(&Bs[nb + 2 * q + 8]);
                    b2 = *reinterpret_cast<const uint32_t*>(&Bs[nb + 16 + 2 * q]);
                    b3 = *reinterpret_cast<const uint32_t*>(&Bs[nb + 16 + 2 * q + 8]);
                }

                const float2 e0 = *reinterpret_cast<const float2*>(cbt + c0a[tt] * CBS_STRIDE + 2 * q);
                const float2 e1 = *reinterpret_cast<const float2*>(cbt + c1a[tt] * CBS_STRIDE + 2 * q);
                const float s0 = (t >= tB0) ? sHi0 : sLo0;
                const float s1 = (t >= tB1) ? sHi1 : sLo1;

                *reinterpret_cast<float2*>(st0 + tt * 8) =
                    make_float2(fmaf(e0.x, s0, c0), fmaf(e0.y, s0, c1));
                *reinterpret_cast<float2*>(st1 + tt * 8) =
                    make_float2(fmaf(e1.x, s1, c2), fmaf(e1.y, s1, c3));
            }
            __syncwarp();
            asm volatile("fence.proxy.async.shared::cta;" ::: "memory");

            if (lid < 16) {
                float* dst = out + gdst_row + (unsigned)(ch * 64);
                uint32_t src = ob_sm + (uint32_t)(lid * OB_STRIDE * 4);
                asm volatile(
                    "cp.async.bulk.global.shared::cta.bulk_group [%0], [%1], 256;"
                    :: "l"(dst), "r"(src) : "memory");
            }
            asm volatile("cp.async.bulk.commit_group;" ::: "memory");
            have_pending = true;

            cA0 = nA0; cA1 = nA1; cB0 = nB0; cB1 = nB1;
        }
    }
    asm volatile("cp.async.bulk.wait_group 0;" ::: "memory");
}

extern "C" void kernel_launch(void* const* d_in, const int* in_sizes, int n_in,
                              void* d_out, int out_size) {
    const float* codebooks = (const float*)d_in[0];
    const int*   codes     = (const int*)  d_in[1];
    const float* scales    = (const float*)d_in[2];
    const float* L         = (const float*)d_in[3];
    const float* R         = (const float*)d_in[4];
    float*       out       = (float*)d_out;

    cudaFuncSetAttribute(qw_pers2_kernel,
                         cudaFuncAttributeMaxDynamicSharedMemorySize, SMEM_TOTAL);

    qw_pers2_kernel<<<GRID_CTAS, THREADS, SMEM_TOTAL>>>(codebooks, codes, scales, L, R, out);
}